// round 8
// baseline (speedup 1.0000x reference)
#include <cuda_runtime.h>
#include <cstdint>

#define MN       1024
#define BATCH    2048
#define DIM      128
#define NITER_F  100.0f
#define ALPHA_F  0.3f
#define SIGMA_F  16.0f

// ---------------- scratch ----------------
__device__ unsigned long long g_part[8][BATCH];  // per-m-block argmin partials
__device__ float g_S[MN * DIM];
__device__ float g_cnt[MN];

__device__ __forceinline__ unsigned int f2ord(float f) {
    unsigned int u = __float_as_uint(f);
    return (u & 0x80000000u) ? ~u : (u | 0x80000000u);
}

__device__ __forceinline__ void ffma2(unsigned long long& acc,
                                      unsigned long long a,
                                      unsigned long long b) {
    asm("fma.rn.f32x2 %0, %1, %2, %0;" : "+l"(acc) : "l"(a), "l"(b));
}

// ---------------- K1: BMU GEMM + argmin (zeroes scratch, computes w2) ------
// tile 128m x 128b, 256 threads, 8m x 8b per thread, FFMA2 pairs along K.
// Smem tiles row-natural with 16B-group XOR swizzle for conflict-free reads.
// Mainloop software-pipelined: wv loads batched (MLP=8), xv prefetched one
// kt-step ahead into a double buffer; unroll 2 lets ptxas rename the copies.
__global__ __launch_bounds__(256, 1)
void k_bmu(const float* __restrict__ x, const float* __restrict__ w) {
    extern __shared__ float smem[];
    float* Ws = smem;                                   // 128*128 f
    float* Xs = smem + 128 * 128;                       // 128*128 f
    unsigned long long* Red =
        (unsigned long long*)(smem + 2 * 128 * 128);    // [16][128]
    float* w2s = (float*)(Red + 16 * 128);              // [128]

    const int m0 = blockIdx.x * 128;
    const int b0 = blockIdx.y * 128;
    const int tid = threadIdx.x;
    const int wrp = tid >> 5, lane = tid & 31;
    const int ty = (lane >> 2) | ((wrp & 1) << 3);      // 0..15
    const int tx = (lane & 3) | ((wrp >> 1) << 2);      // 0..15

    // fold scratch zeroing into this kernel (completes before k_scatter)
    {
        int z = blockIdx.y * 8 + blockIdx.x;            // 0..127
        *(float4*)&g_S[z * 1024 + tid * 4] = make_float4(0.f, 0.f, 0.f, 0.f);
        if (tid < 2)
            *(float4*)&g_cnt[z * 8 + tid * 4] = make_float4(0.f, 0.f, 0.f, 0.f);
    }

    // stage both tiles (LDG.128 -> swizzled ST.128)
    #pragma unroll
    for (int i = 0; i < 16; i++) {
        int idx = tid + i * 256;          // 0..4095
        int row = idx >> 5;               // 0..127
        int g   = idx & 31;               // float4 group
        int sg  = (g ^ ((row >> 3) & 7)) << 2;
        float4 v = *(const float4*)&w[(m0 + row) * DIM + g * 4];
        *(float4*)&Ws[row * 128 + sg] = v;
        float4 u = *(const float4*)&x[(b0 + row) * DIM + g * 4];
        *(float4*)&Xs[row * 128 + sg] = u;
    }
    __syncthreads();

    // w2 from the staged tile (swizzle is a within-row permutation)
    if (tid < 128) {
        float s = 0.0f;
        #pragma unroll
        for (int g = 0; g < 32; g++) {
            float4 v = *(const float4*)&Ws[tid * 128 + g * 4];
            s += v.x * v.x + v.y * v.y + v.z * v.z + v.w * v.w;
        }
        w2s[tid] = s;
    }

    unsigned long long acc[8][8];
    #pragma unroll
    for (int mi = 0; mi < 8; mi++)
        #pragma unroll
        for (int bj = 0; bj < 8; bj++) acc[mi][bj] = 0ULL;

    const float* wbase = &Ws[(ty * 8) * 128];
    const float* xbase = &Xs[(tx * 8) * 128];
    const int sw = ty & 7;
    const int sx = tx & 7;

    // prologue: xv for kt=0
    ulonglong2 xv[8];
    {
        const int ox0 = (0 ^ sx) << 2;
        #pragma unroll
        for (int bj = 0; bj < 8; bj++)
            xv[bj] = *(const ulonglong2*)&xbase[bj * 128 + ox0];
    }

    #pragma unroll 2
    for (int kt = 0; kt < 32; kt++) {      // 4 k per step
        const int ow = (kt ^ sw) << 2;
        // batched wv loads (MLP=8)
        ulonglong2 wv[8];
        #pragma unroll
        for (int mi = 0; mi < 8; mi++)
            wv[mi] = *(const ulonglong2*)&wbase[mi * 128 + ow];
        // prefetch next step's xv
        ulonglong2 xn[8];
        const int oxn = (((kt + 1) & 31) ^ sx) << 2;
        #pragma unroll
        for (int bj = 0; bj < 8; bj++)
            xn[bj] = *(const ulonglong2*)&xbase[bj * 128 + oxn];
        // 128 FFMA2
        #pragma unroll
        for (int mi = 0; mi < 8; mi++) {
            #pragma unroll
            for (int bj = 0; bj < 8; bj++) {
                ffma2(acc[mi][bj], wv[mi].x, xv[bj].x);
                ffma2(acc[mi][bj], wv[mi].y, xv[bj].y);
            }
        }
        #pragma unroll
        for (int bj = 0; bj < 8; bj++) xv[bj] = xn[bj];
    }
    __syncthreads();   // w2s ready

    float w2r[8];
    #pragma unroll
    for (int mi = 0; mi < 8; mi++) w2r[mi] = w2s[ty * 8 + mi];

    #pragma unroll
    for (int bj = 0; bj < 8; bj++) {
        unsigned long long best = 0xFFFFFFFFFFFFFFFFULL;
        #pragma unroll
        for (int mi = 0; mi < 8; mi++) {
            float lo = __uint_as_float((unsigned int)(acc[mi][bj]));
            float hi = __uint_as_float((unsigned int)(acc[mi][bj] >> 32));
            float d2 = w2r[mi] - 2.0f * (lo + hi);
            unsigned long long key =
                ((unsigned long long)f2ord(d2) << 32) |
                (unsigned long long)(m0 + ty * 8 + mi);
            best = min(best, key);
        }
        Red[ty * 128 + tx * 8 + bj] = best;
    }
    __syncthreads();

    if (tid < 128) {
        unsigned long long best = Red[tid];
        #pragma unroll
        for (int t = 1; t < 16; t++) best = min(best, Red[t * 128 + tid]);
        g_part[blockIdx.x][b0 + tid] = best;   // plain store, no atomics
    }
}

// ---------------- K2: reduce partials + scatter x rows into BMU bins --------
__global__ void k_scatter(const float* __restrict__ x) {
    int warp = (blockIdx.x * blockDim.x + threadIdx.x) >> 5;  // 0..2047
    int lane = threadIdx.x & 31;
    if (warp >= BATCH) return;

    unsigned long long v = (lane < 8) ? g_part[lane][warp]
                                      : 0xFFFFFFFFFFFFFFFFULL;
    #pragma unroll
    for (int o = 4; o >= 1; o >>= 1)
        v = min(v, __shfl_xor_sync(0xffffffffu, v, o));
    v = __shfl_sync(0xffffffffu, v, 0);
    int m = (int)(v & 0xFFFFFFFFULL);

    float4 vv = *(const float4*)&x[warp * DIM + lane * 4];
    float* dst = &g_S[m * DIM + lane * 4];
    asm volatile("red.global.add.v4.f32 [%0], {%1, %2, %3, %4};"
                 :: "l"(dst), "f"(vv.x), "f"(vv.y), "f"(vv.z), "f"(vv.w)
                 : "memory");
    if (lane == 0) atomicAdd(&g_cnt[m], 1.0f);
}

// ---------------- K3: fused separable gaussian contraction + update ---------
// 128 blocks = (cx, d-quarter), 256 threads.
__global__ __launch_bounds__(256)
void k_tail(const float* __restrict__ w,
            const int* __restrict__ it,
            float* __restrict__ out) {
    __shared__ float4 Ts[32][9];     // [by][dq], padded
    __shared__ float tc_s[32];
    __shared__ float e_s[32];

    const int cx = blockIdx.x & 31;
    const int d0 = (blockIdx.x >> 5) * 32;   // d-quarter base
    const int tid = threadIdx.x;

    float lr_decay = 1.0f - (float)it[0] / NITER_F;
    float alpha_op = ALPHA_F * lr_decay;
    float sig = SIGMA_F * lr_decay;
    float inv_s2 = 1.0f / (sig * sig);

    if (tid < 32) e_s[tid] = expf(-(float)(tid * tid) * inv_s2);
    __syncthreads();

    // stage A: Ts[by][d] = sum_bx e(|cx-bx|) * S[by*32+bx][d]
    {
        const int by = tid >> 3;           // 0..31
        const int dq = tid & 7;            // float4 index
        const int d  = d0 + dq * 4;
        float4 a = make_float4(0.f, 0.f, 0.f, 0.f);
        #pragma unroll
        for (int bb = 0; bb < 4; bb++) {
            float4 sv[8];
            #pragma unroll
            for (int j = 0; j < 8; j++)
                sv[j] = *(const float4*)&g_S[(by * 32 + bb * 8 + j) * DIM + d];
            #pragma unroll
            for (int j = 0; j < 8; j++) {
                float e = e_s[abs(cx - (bb * 8 + j))];
                a.x += e * sv[j].x; a.y += e * sv[j].y;
                a.z += e * sv[j].z; a.w += e * sv[j].w;
            }
        }
        Ts[by][dq] = a;
    }
    if (tid < 32) {
        float c = 0.0f;
        #pragma unroll
        for (int bx = 0; bx < 32; bx++)
            c += e_s[abs(cx - bx)] * g_cnt[tid * 32 + bx];
        tc_s[tid] = c;
    }
    __syncthreads();

    // stage B
    {
        const int cy = tid >> 3;
        const int dq = tid & 7;
        const int d  = d0 + dq * 4;
        float4 a = make_float4(0.f, 0.f, 0.f, 0.f);
        float s = 0.0f;
        #pragma unroll
        for (int by = 0; by < 32; by++) {
            float e = e_s[abs(cy - by)];
            float4 t = Ts[by][dq];
            a.x += e * t.x; a.y += e * t.y;
            a.z += e * t.z; a.w += e * t.w;
            s += e * tc_s[by];
        }
        const int c = (cy * 32 + cx) * DIM + d;
        float4 wv = *(const float4*)&w[c];
        float4 o;
        o.x = wv.x + alpha_op * (a.x - s * wv.x);
        o.y = wv.y + alpha_op * (a.y - s * wv.y);
        o.z = wv.z + alpha_op * (a.z - s * wv.z);
        o.w = wv.w + alpha_op * (a.w - s * wv.w);
        *(float4*)&out[c] = o;
    }
}

// ---------------- launch ----------------
extern "C" void kernel_launch(void* const* d_in, const int* in_sizes, int n_in,
                              void* d_out, int out_size) {
    const float* x   = (const float*)d_in[0];   // [2048,128]
    const float* w   = (const float*)d_in[1];   // [1024,128]
    const int*   it  = (const int*)d_in[3];
    float* out = (float*)d_out;

    const int bmu_smem = 2 * 128 * 128 * 4 + 16 * 128 * 8 + 128 * 4;
    cudaFuncSetAttribute(k_bmu, cudaFuncAttributeMaxDynamicSharedMemorySize,
                         bmu_smem);

    k_bmu<<<dim3(8, 16), 256, bmu_smem>>>(x, w);
    k_scatter<<<256, 256>>>(x);
    k_tail<<<128, 256>>>(w, it, out);
}